// round 2
// baseline (speedup 1.0000x reference)
#include <cuda_runtime.h>
#include <cuda_fp16.h>

#define BB 2
#define LL 16
#define CC 16
#define HH 64
#define WW 64
#define HW (HH*WW)

// Channel-last fp16 image cache: index [((b*L+l)*HW + p)*2 + q] of uint4 (8 halves each)
__device__ uint4 g_imgH[BB*LL*HW*2];

// ---------------------------------------------------------------------------
// Kernel 1: transpose images (B,L,C,H,W) fp32 -> channel-last fp16.
// One thread per pixel: 16 coalesced strided reads, 32B contiguous write.
// ---------------------------------------------------------------------------
__global__ __launch_bounds__(256) void trans_kernel(const float* __restrict__ images) {
    int i = blockIdx.x * 256 + threadIdx.x;     // [0, BB*LL*HW)
    int bl  = i >> 12;
    int pix = i & (HW - 1);
    const float* s = images + (size_t)bl * CC * HW + pix;

    unsigned int u[8];
#pragma unroll
    for (int c = 0; c < 8; c++) {
        float f0 = s[(2 * c + 0) * HW];
        float f1 = s[(2 * c + 1) * HW];
        __half2 h = __floats2half2_rn(f0, f1);
        u[c] = *(unsigned int*)&h;
    }
    uint4* d = g_imgH + (size_t)i * 2;
    d[0] = make_uint4(u[0], u[1], u[2], u[3]);
    d[1] = make_uint4(u[4], u[5], u[6], u[7]);
}

// ---------------------------------------------------------------------------
// Kernel 2: main. Block = 128 pixels x 2 channel-octets for one (b,t).
// Cumsum of flows is fused (computed per block into smem).
// ---------------------------------------------------------------------------
__device__ __forceinline__ void accum8(float* acc, uint4 u, float w) {
    float2 f;
    f = __half22float2(*(__half2*)&u.x); acc[0] += w * f.x; acc[1] += w * f.y;
    f = __half22float2(*(__half2*)&u.y); acc[2] += w * f.x; acc[3] += w * f.y;
    f = __half22float2(*(__half2*)&u.z); acc[4] += w * f.x; acc[5] += w * f.y;
    f = __half22float2(*(__half2*)&u.w); acc[6] += w * f.x; acc[7] += w * f.y;
}

__global__ __launch_bounds__(256) void main_kernel(const float* __restrict__ flows,
                                                   float* __restrict__ out) {
    __shared__ float scum[LL * 128 * 2];   // [l][pixel][comp], 16KB

    int bt  = blockIdx.x >> 5;        // 32 blocks per (b,t)
    int blk = blockIdx.x & 31;
    int b   = bt >> 4;
    int t   = 15 - (bt & 15);         // heavy blocks first
    int p_base = blk * 128;
    int tid = threadIdx.x;

    // Fused cumsum: 256 threads = 128 pixels x 2 components.
    {
        int comp = tid >> 7;
        int pl   = tid & 127;
        const float* fb = flows + ((size_t)b * LL * 2 + comp) * HW + p_base + pl;
        float v[LL];
#pragma unroll
        for (int l = 0; l < LL; l++) v[l] = fb[l * 2 * HW];
        float c = 0.0f;
#pragma unroll
        for (int l = 0; l < LL; l++) {
            c += v[l];
            scum[(l * 128 + pl) * 2 + comp] = c;
        }
    }
    __syncthreads();

    int pl = tid & 127;
    int c8 = tid >> 7;                // which channel-octet
    int p  = p_base + pl;
    int h  = p >> 6;
    int w  = p & 63;

    float bx = (w + 0.5f) * (2.0f / WW) - 1.0f;
    float by = (h + 0.5f) * (2.0f / HH) - 1.0f;
    float ctx = scum[(t * 128 + pl) * 2 + 0];
    float cty = scum[(t * 128 + pl) * 2 + 1];

    float acc[8] = {0.f, 0.f, 0.f, 0.f, 0.f, 0.f, 0.f, 0.f};
    const uint4* ib = g_imgH + ((size_t)b * LL * HW) * 2 + c8;

    for (int k = 0; k <= t; k++) {
        float ckx = scum[(k * 128 + pl) * 2 + 0];
        float cky = scum[(k * 128 + pl) * 2 + 1];
        float gx = bx + (ctx - ckx);
        float gy = by + (cty - cky);

        // wrap: mod(g+1, 2) - 1, then safety clamp (matches reference)
        float ux = gx + 1.0f; ux -= floorf(ux * 0.5f) * 2.0f; gx = ux - 1.0f;
        if (gx < -1.0f) gx += 2.0f;
        float uy = gy + 1.0f; uy -= floorf(uy * 0.5f) * 2.0f; gy = uy - 1.0f;
        if (gy < -1.0f) gy += 2.0f;

        float rx = (gx + 1.0f) * 0.5f * (float)WW - 0.5f;
        float ry = (gy + 1.0f) * 0.5f * (float)HH - 0.5f;

        float fx0 = floorf(rx), fy0 = floorf(ry);
        int x0 = (int)fx0, y0 = (int)fy0;
        float ax = (fx0 + 1.0f) - rx;     // fx1 - rx
        float sx = rx - fx0;
        float ay = (fy0 + 1.0f) - ry;
        float sy = ry - fy0;

        float mx0 = (x0 >= 0)     ? 1.0f : 0.0f;
        float mx1 = (x0 < WW - 1) ? 1.0f : 0.0f;
        float my0 = (y0 >= 0)     ? 1.0f : 0.0f;
        float my1 = (y0 < HH - 1) ? 1.0f : 0.0f;

        float wa = ax * ay * mx0 * my0;   // (x0, y0)
        float wb = ax * sy * mx0 * my1;   // (x0, y1)
        float wc = sx * ay * mx1 * my0;   // (x1, y0)
        float wd = sx * sy * mx1 * my1;   // (x1, y1)

        int x0c = max(x0, 0), x1c = min(x0 + 1, WW - 1);
        int y0c = max(y0, 0), y1c = min(y0 + 1, HH - 1);

        const uint4* kb = ib + (size_t)k * HW * 2;
        uint4 va = kb[(y0c * WW + x0c) * 2];
        uint4 vb = kb[(y1c * WW + x0c) * 2];
        uint4 vc = kb[(y0c * WW + x1c) * 2];
        uint4 vd = kb[(y1c * WW + x1c) * 2];

        accum8(acc, va, wa);
        accum8(acc, vb, wb);
        accum8(acc, vc, wc);
        accum8(acc, vd, wd);
    }

    // out layout (B,L,C,H,W), this thread owns channels [c8*8, c8*8+8)
    float* ob = out + ((size_t)(b * LL + t) * CC + c8 * 8) * HW + p;
#pragma unroll
    for (int r = 0; r < 8; r++) ob[r * HW] = acc[r];
}

// ---------------------------------------------------------------------------
extern "C" void kernel_launch(void* const* d_in, const int* in_sizes, int n_in,
                              void* d_out, int out_size) {
    const float* flows  = (const float*)d_in[0];
    const float* images = (const float*)d_in[1];
    if (n_in >= 2 && in_sizes[0] > in_sizes[1]) {   // defensive: ensure flows is smaller
        const float* tmp = flows; flows = images; images = tmp;
    }
    float* out = (float*)d_out;

    trans_kernel<<<BB * LL * HW / 256, 256>>>(images);
    main_kernel<<<BB * LL * 32, 256>>>(flows, out);
}

// round 4
// speedup vs baseline: 1.3070x; 1.3070x over previous
#include <cuda_runtime.h>
#include <cuda_fp16.h>

#define BB 2
#define LL 16
#define CC 16
#define HH 64
#define WW 64
#define HW (HH*WW)

// Channel-last fp16 image cache: pixel chunk = 32B (16 halves), stored as 2 uint4.
// Index: ((bl*HW + y*WW + x) * 2 + half_chunk)
__device__ uint4 g_imgH[BB*LL*HW*2];

// ---------------------------------------------------------------------------
// Kernel 1: transpose images (B,L,C,H,W) fp32 -> channel-last fp16
// ---------------------------------------------------------------------------
__global__ __launch_bounds__(256) void trans_kernel(const float* __restrict__ images) {
    int i = blockIdx.x * 256 + threadIdx.x;     // [0, BB*LL*HW)
    int bl  = i >> 12;
    int pix = i & (HW - 1);
    const float* s = images + (size_t)bl * CC * HW + pix;

    unsigned int u[8];
#pragma unroll
    for (int c = 0; c < 8; c++) {
        float f0 = s[(2 * c + 0) * HW];
        float f1 = s[(2 * c + 1) * HW];
        __half2 hh = __floats2half2_rn(f0, f1);
        u[c] = *(unsigned int*)&hh;
    }
    uint4* d = g_imgH + (size_t)i * 2;
    d[0] = make_uint4(u[0], u[1], u[2], u[3]);
    d[1] = make_uint4(u[4], u[5], u[6], u[7]);
}

// ---------------------------------------------------------------------------
// Kernel 2: main. 4 lanes per pixel: q = (xq<<1)|cq
//   xq: 0 = left column (x0), 1 = right column (x1)
//   cq: 0 = channels 0-7,     1 = channels 8-15
// Per k each lane loads 2x16B (top/bottom row at its column), accumulates its
// x-corner's weighted contribution; shfl_xor(2) merges left+right at the end.
// ---------------------------------------------------------------------------
__device__ __forceinline__ void accum8(float* acc, uint4 u, float w) {
    float2 f;
    f = __half22float2(*(__half2*)&u.x); acc[0] += w * f.x; acc[1] += w * f.y;
    f = __half22float2(*(__half2*)&u.y); acc[2] += w * f.x; acc[3] += w * f.y;
    f = __half22float2(*(__half2*)&u.z); acc[4] += w * f.x; acc[5] += w * f.y;
    f = __half22float2(*(__half2*)&u.w); acc[6] += w * f.x; acc[7] += w * f.y;
}

__global__ __launch_bounds__(256) void main_kernel(const float* __restrict__ flows,
                                                   float* __restrict__ out) {
    __shared__ float2 scum[LL * 64];   // [l][pixel], 8KB

    int bt  = blockIdx.x >> 6;        // 64 blocks per (b,t), 64 pixels each
    int blk = blockIdx.x & 63;
    int b   = bt >> 4;
    int t   = 15 - (bt & 15);         // heavy blocks first
    int p_base = blk * 64;
    int tid = threadIdx.x;

    // Fused cumsum: threads 0..127 = 64 pixels x 2 components.
    if (tid < 128) {
        int comp = tid >> 6;
        int pl   = tid & 63;
        const float* fb = flows + ((size_t)b * LL * 2 + comp) * HW + p_base + pl;
        float c = 0.0f;
#pragma unroll
        for (int l = 0; l < LL; l++) {
            c += fb[l * 2 * HW];
            ((float*)&scum[l * 64 + pl])[comp] = c;
        }
    }
    __syncthreads();

    int pl = tid >> 2;
    int q  = tid & 3;
    int xq = q >> 1;                  // left/right column
    int cq = q & 1;                   // channel octet
    int p  = p_base + pl;
    int h  = p >> 6;
    int w  = p & 63;

    float bx = (w + 0.5f) * (2.0f / WW) - 1.0f;
    float by = (h + 0.5f) * (2.0f / HH) - 1.0f;
    float2 ct = scum[t * 64 + pl];

    float acc[8] = {0.f, 0.f, 0.f, 0.f, 0.f, 0.f, 0.f, 0.f};
    const uint4* ib = g_imgH + (size_t)b * LL * HW * 2 + cq;

    for (int k = 0; k <= t; k++) {
        float2 ck = scum[k * 64 + pl];
        float gx = bx + (ct.x - ck.x);
        float gy = by + (ct.y - ck.y);

        // wrap: mod(g+1, 2) - 1, then safety clamp (matches reference)
        float ux = gx + 1.0f; ux -= floorf(ux * 0.5f) * 2.0f; gx = ux - 1.0f;
        if (gx < -1.0f) gx += 2.0f;
        float uy = gy + 1.0f; uy -= floorf(uy * 0.5f) * 2.0f; gy = uy - 1.0f;
        if (gy < -1.0f) gy += 2.0f;

        float rx = (gx + 1.0f) * 0.5f * (float)WW - 0.5f;
        float ry = (gy + 1.0f) * 0.5f * (float)HH - 0.5f;

        float fx0 = floorf(rx), fy0 = floorf(ry);
        int x0 = (int)fx0, y0 = (int)fy0;     // x0,y0 in [-1,63]
        float ax = (fx0 + 1.0f) - rx;         // left-corner x weight
        float sx = rx - fx0;                  // right-corner x weight
        float ay = (fy0 + 1.0f) - ry;
        float sy = ry - fy0;

        // This lane's x-corner weight with in-bounds mask
        float xwl = (x0 >= 0)     ? ax : 0.0f;   // x0 <= 63 always
        float xwr = (x0 < WW - 1) ? sx : 0.0f;   // x1 = x0+1 valid
        float xw  = xq ? xwr : xwl;
        float wt  = xw * ((y0 >= 0)     ? ay : 0.0f);   // top row (y0)
        float wbm = xw * ((y0 < HH - 1) ? sy : 0.0f);   // bottom row (y1)

        int xc  = min(max(x0 + xq, 0), WW - 1);
        int y0c = max(y0, 0);
        int y1c = min(y0 + 1, HH - 1);

        const uint4* kb = ib + (size_t)k * HW * 2;
        uint4 vt = kb[(y0c * WW + xc) * 2];
        uint4 vb = kb[(y1c * WW + xc) * 2];

        accum8(acc, vt, wt);
        accum8(acc, vb, wbm);
    }

    // Merge left/right columns: partner lane is q ^ 2 (same pixel, same octet)
#pragma unroll
    for (int r = 0; r < 8; r++)
        acc[r] += __shfl_xor_sync(0xffffffffu, acc[r], 2);

    if (xq == 0) {
        // out layout (B,L,C,H,W); this lane owns channels [cq*8, cq*8+8)
        float* ob = out + ((size_t)(b * LL + t) * CC + cq * 8) * HW + p;
#pragma unroll
        for (int r = 0; r < 8; r++) ob[r * HW] = acc[r];
    }
}

// ---------------------------------------------------------------------------
extern "C" void kernel_launch(void* const* d_in, const int* in_sizes, int n_in,
                              void* d_out, int out_size) {
    const float* flows  = (const float*)d_in[0];
    const float* images = (const float*)d_in[1];
    if (n_in >= 2 && in_sizes[0] > in_sizes[1]) {   // defensive: flows is smaller
        const float* tmp = flows; flows = images; images = tmp;
    }
    float* out = (float*)d_out;

    trans_kernel<<<BB * LL * HW / 256, 256>>>(images);
    main_kernel<<<BB * LL * 64, 256>>>(flows, out);
}